// round 15
// baseline (speedup 1.0000x reference)
#include <cuda_runtime.h>
#include <cuda_bf16.h>
#include <cstdint>

#define N1 262144
#define N2 65536
#define KNN 16
#define MPAIR (N2*KNN)
#define EPSV 1e-5f

#define N2_JOBS2 (N2/256)          // 256  (each: upfeat+pre, 256 rows)
#define N1_JOBS2 (N1/256)          // 1024 (each: 256 rows)
#define ALL_JOBS (N1_JOBS2 + N2_JOBS2)

// ---- static scratch (no runtime allocation allowed) ----
__device__ float    g_upfeat[N2*64];   // relu(bn(x2@w2^T))
__device__ float    g_pre[N2*64];      // x2-part of shrinker linear
__device__ float    g_e[MPAIR];        // exp(logit)
__device__ float    g_denom[N1];       // softmax denominator
__device__ float4   g_p1q[N1];         // packed p1 (xyz_)
__device__ float4   g_p2q[N2];         // packed p2 (xyz_)
__device__ uint32_t g_packW[3*4096];   // prepacked+swizzled bf16 hi/lo weights (w1,w2,ws1)
__device__ float    g_fbW[3*64];       // folded biases
__device__ float4   g_sw34[64];        // shrinker (w3x,w3y,w3z,w2) per channel

// bf16 mma (baseline ISA, sm_80+; lowers to HMMA on sm_103 tensor pipe)
__device__ __forceinline__ void mma16816(float* d, const uint32_t* a, uint32_t b0, uint32_t b1) {
    asm volatile(
        "mma.sync.aligned.m16n8k16.row.col.f32.bf16.bf16.f32 "
        "{%0,%1,%2,%3}, {%4,%5,%6,%7}, {%8,%9}, {%0,%1,%2,%3};"
        : "+f"(d[0]), "+f"(d[1]), "+f"(d[2]), "+f"(d[3])
        : "r"(a[0]), "r"(a[1]), "r"(a[2]), "r"(a[3]), "r"(b0), "r"(b1));
}

// split (f0,f1) -> packed bf16 hi-pair + lo-pair (residual). Bit-trick version.
__device__ __forceinline__ void split2(float f0, float f1, uint32_t& hi, uint32_t& lo) {
    uint32_t hp;
    asm("cvt.rn.bf16x2.f32 %0, %1, %2;" : "=r"(hp) : "f"(f1), "f"(f0));
    float h0 = __uint_as_float(hp << 16);
    float h1 = __uint_as_float(hp & 0xFFFF0000u);
    float l0 = f0 - h0, l1 = f1 - h1;
    uint32_t lp;
    asm("cvt.rn.bf16x2.f32 %0, %1, %2;" : "=r"(lp) : "f"(l1), "f"(l0));
    hi = hp; lo = lp;
}

// ============ prep: pack all weights once + folded biases + sw34 + init ============
__global__ void __launch_bounds__(256)
prep_kernel(const float* __restrict__ w1, const float* __restrict__ b1,
            const float* __restrict__ g1, const float* __restrict__ be1,
            const float* __restrict__ m1, const float* __restrict__ v1,
            const float* __restrict__ w2, const float* __restrict__ b2,
            const float* __restrict__ g2, const float* __restrict__ be2,
            const float* __restrict__ m2, const float* __restrict__ v2,
            const float* __restrict__ ws1, const float* __restrict__ bs1,
            const float* __restrict__ gs, const float* __restrict__ bes,
            const float* __restrict__ ms, const float* __restrict__ vs,
            const float* __restrict__ ws2,
            const float* __restrict__ p1, const float* __restrict__ p2)
{
    const int gid = blockIdx.x * 256 + threadIdx.x;

    if (gid < 3 * 4096) {
        int mat = gid >> 12, idx = gid & 4095;
        const float *w, *gg, *vv; int wstride, wcol0;
        if (mat == 0)      { w = w1;  gg = g1; vv = v1; wstride = 64; wcol0 = 0; }
        else if (mat == 1) { w = w2;  gg = g2; vv = v2; wstride = 64; wcol0 = 0; }
        else               { w = ws1; gg = gs; vv = vs; wstride = 67; wcol0 = 3; }
        int row = idx >> 6, col = idx & 63;
        int r31 = row & 31;
        int ks = r31 >> 3, q = r31 & 7;
        int kk = 16 * ks + ((q < 4) ? 4 * q : 4 * (q - 4) + 2);
        float s  = gg[col] * rsqrtf(vv[col] + EPSV);
        float w0 = w[col * wstride + wcol0 + kk]     * s;
        float wv = w[col * wstride + wcol0 + kk + 1] * s;
        uint32_t hiw, low;
        split2(w0, wv, hiw, low);
        g_packW[mat * 4096 + row * 64 + (col ^ ((row & 3) << 3))] = (row < 32) ? hiw : low;
    } else if (gid < 3 * 4096 + 192) {
        int t = gid - 3 * 4096; int mat = t >> 6, c = t & 63;
        const float *bb, *gg, *be, *mm, *vv;
        if (mat == 0)      { bb = b1;  gg = g1; be = be1; mm = m1; vv = v1; }
        else if (mat == 1) { bb = b2;  gg = g2; be = be2; mm = m2; vv = v2; }
        else               { bb = bs1; gg = gs; be = bes; mm = ms; vv = vs; }
        float s = gg[c] * rsqrtf(vv[c] + EPSV);
        g_fbW[mat * 64 + c] = (bb[c] - mm[c]) * s + be[c];
    } else if (gid < 3 * 4096 + 192 + 64) {
        int c = gid - (3 * 4096 + 192);
        float s = gs[c] * rsqrtf(vs[c] + EPSV);
        g_sw34[c] = make_float4(ws1[c * 67] * s, ws1[c * 67 + 1] * s,
                                ws1[c * 67 + 2] * s, ws2[c]);
    }

    const int tot = gridDim.x * 256;
    for (int i = gid; i < N1; i += tot) {
        g_denom[i] = 0.0f;
        g_p1q[i] = make_float4(p1[3*i], p1[3*i+1], p1[3*i+2], 0.f);
    }
    for (int i = gid; i < N2; i += tot)
        g_p2q[i] = make_float4(p2[3*i], p2[3*i+1], p2[3*i+2], 0.f);
}

__device__ __forceinline__ void load_A(const float* __restrict__ x, int m0, int gq, int tq,
                                       uint32_t Ah[4][4], uint32_t Al[4][4])
{
    const float4* r0 = (const float4*)(x + (size_t)(m0 + gq) * 64);
    const float4* r1 = (const float4*)(x + (size_t)(m0 + gq + 8) * 64);
    #pragma unroll
    for (int ks = 0; ks < 4; ks++) {
        float4 v0 = r0[4 * ks + tq];
        float4 v1 = r1[4 * ks + tq];
        split2(v0.x, v0.y, Ah[ks][0], Al[ks][0]);
        split2(v1.x, v1.y, Ah[ks][1], Al[ks][1]);
        split2(v0.z, v0.w, Ah[ks][2], Al[ks][2]);
        split2(v1.z, v1.w, Ah[ks][3], Al[ks][3]);
    }
}

// DUAL-A 3-chain MMA over half the n-tiles. Per (ks,nt): 4 LDS serve 6 MMAs.
__device__ __forceinline__ void run_chains_dual(float acc0[4][4], float acc1[4][4],
                                                const uint32_t* packB,
                                                const uint32_t Ah0[4][4], const uint32_t Al0[4][4],
                                                const uint32_t Ah1[4][4], const uint32_t Al1[4][4],
                                                int gq, int tq, int nt0)
{
    const int csw = tq << 3;
    #pragma unroll
    for (int ks = 0; ks < 4; ks++) {
        const int rh0 = (8 * ks + tq) * 64;
        const int rh1 = (8 * ks + tq + 4) * 64;
        const int rl0 = (32 + 8 * ks + tq) * 64;
        const int rl1 = (32 + 8 * ks + tq + 4) * 64;
        #pragma unroll
        for (int nt = 0; nt < 4; nt++) {
            const int coff = (8 * (nt0 + nt) + gq) ^ csw;
            uint32_t bh0 = packB[rh0 + coff], bh1 = packB[rh1 + coff];
            uint32_t bl0 = packB[rl0 + coff], bl1 = packB[rl1 + coff];
            mma16816(acc0[nt], Ah0[ks], bh0, bh1);
            mma16816(acc1[nt], Ah1[ks], bh0, bh1);
            mma16816(acc0[nt], Ah0[ks], bl0, bl1);
            mma16816(acc1[nt], Ah1[ks], bl0, bl1);
            mma16816(acc0[nt], Al0[ks], bh0, bh1);
            mma16816(acc1[nt], Al1[ks], bh0, bh1);
        }
    }
}

// epilogue: folded bias read from GLOBAL (L1-cached, tiny)
__device__ __forceinline__ void epilogue_half(float acc[4][4], const float* __restrict__ fb,
                                              float* __restrict__ o, int m0, int gq, int tq,
                                              int nt0, bool relu)
{
    float* o0 = o + (size_t)(m0 + gq) * 64;
    float* o1 = o + (size_t)(m0 + gq + 8) * 64;
    #pragma unroll
    for (int nt = 0; nt < 4; nt++) {
        int col = 8 * (nt0 + nt) + 2 * tq;
        float2 fbp = *(const float2*)(fb + col);
        float2 u, v;
        u.x = acc[nt][0] + fbp.x; u.y = acc[nt][1] + fbp.y;
        v.x = acc[nt][2] + fbp.x; v.y = acc[nt][3] + fbp.y;
        if (relu) {
            u.x = fmaxf(u.x, 0.f); u.y = fmaxf(u.y, 0.f);
            v.x = fmaxf(v.x, 0.f); v.y = fmaxf(v.y, 0.f);
        }
        *(float2*)(o0 + col) = u;
        *(float2*)(o1 + col) = v;
    }
}

// ====== ALL GEMM tiles, 256-row dual-A jobs: 256 n2 jobs (first) + 1024 n1 jobs ======
__global__ void __launch_bounds__(256, 2)
gemm_all_kernel(const float* __restrict__ x1, const float* __restrict__ x2,
                float* __restrict__ outp)
{
    __shared__ uint32_t packW[3 * 4096];   // 48 KB
    const int tid = threadIdx.x, wid = tid >> 5, lane = tid & 31;
    const int gq = lane >> 2, tq = lane & 3;

    {
        const float4* src = (const float4*)g_packW;
        #pragma unroll
        for (int it = 0; it < 12; it++)
            ((float4*)packW)[it * 256 + tid] = src[it * 256 + tid];
    }
    __syncthreads();

    for (int job = blockIdx.x; job < ALL_JOBS; job += gridDim.x) {
        if (job < N2_JOBS2) {
            const int m0 = job * 256 + wid * 16;
            const int m1 = m0 + 128;
            uint32_t Ah0[4][4], Al0[4][4], Ah1[4][4], Al1[4][4];
            load_A(x2, m0, gq, tq, Ah0, Al0);
            load_A(x2, m1, gq, tq, Ah1, Al1);
            #pragma unroll
            for (int half = 0; half < 2; half++) {
                float acc0[4][4], acc1[4][4];
                #pragma unroll
                for (int nt = 0; nt < 4; nt++)
                    #pragma unroll
                    for (int r = 0; r < 4; r++) { acc0[nt][r] = 0.f; acc1[nt][r] = 0.f; }
                run_chains_dual(acc0, acc1, packW + 4096, Ah0, Al0, Ah1, Al1, gq, tq, half * 4);
                epilogue_half(acc0, g_fbW + 64, g_upfeat, m0, gq, tq, half * 4, true);
                epilogue_half(acc1, g_fbW + 64, g_upfeat, m1, gq, tq, half * 4, true);

                #pragma unroll
                for (int nt = 0; nt < 4; nt++)
                    #pragma unroll
                    for (int r = 0; r < 4; r++) { acc0[nt][r] = 0.f; acc1[nt][r] = 0.f; }
                run_chains_dual(acc0, acc1, packW + 8192, Ah0, Al0, Ah1, Al1, gq, tq, half * 4);
                epilogue_half(acc0, g_fbW + 128, g_pre, m0, gq, tq, half * 4, false);
                epilogue_half(acc1, g_fbW + 128, g_pre, m1, gq, tq, half * 4, false);
            }
        } else {
            const int m0 = (job - N2_JOBS2) * 256 + wid * 16;
            const int m1 = m0 + 128;
            uint32_t Ah0[4][4], Al0[4][4], Ah1[4][4], Al1[4][4];
            load_A(x1, m0, gq, tq, Ah0, Al0);
            load_A(x1, m1, gq, tq, Ah1, Al1);
            #pragma unroll
            for (int half = 0; half < 2; half++) {
                float acc0[4][4], acc1[4][4];
                #pragma unroll
                for (int nt = 0; nt < 4; nt++)
                    #pragma unroll
                    for (int r = 0; r < 4; r++) { acc0[nt][r] = 0.f; acc1[nt][r] = 0.f; }
                run_chains_dual(acc0, acc1, packW, Ah0, Al0, Ah1, Al1, gq, tq, half * 4);
                epilogue_half(acc0, g_fbW, outp, m0, gq, tq, half * 4, true);
                epilogue_half(acc1, g_fbW, outp, m1, gq, tq, half * 4, true);
            }
        }
    }
}

// ========== logit + exp + denom, ILP-2: each thread handles pairs mi and mi+256 ==========
// The two pairs' gathers (p1q) and pre-row loads interleave, hiding the ~600-cyc
// random-gather latency that bounded the ILP-1 version.
__global__ void __launch_bounds__(256)
logit_kernel(const int* __restrict__ knn, const float* __restrict__ bs2)
{
    __shared__ float4 smem_q[64];
    const int tid = threadIdx.x;
    if (tid < 64) smem_q[tid] = g_sw34[tid];
    __syncthreads();
    const float bias2 = bs2[0];

    const int miA = blockIdx.x * 512 + tid;
    const int miB = miA + 256;
    const int jA = miA >> 4, jB = miB >> 4;
    const int iA = knn[miA], iB = knn[miB];
    float4 pqA = g_p1q[iA];
    float4 pqB = g_p1q[iB];
    float4 qqA = g_p2q[jA];
    float4 qqB = g_p2q[jB];
    float paX = pqA.x - qqA.x, paY = pqA.y - qqA.y, paZ = pqA.z - qqA.z;
    float pbX = pqB.x - qqB.x, pbY = pqB.y - qqB.y, pbZ = pqB.z - qqB.z;

    float accA = 0.0f, accB = 0.0f;
    const float4* preA = (const float4*)(g_pre + (size_t)jA * 64);
    const float4* preB = (const float4*)(g_pre + (size_t)jB * 64);
    #pragma unroll
    for (int c4 = 0; c4 < 16; c4++) {
        float4 pvA = preA[c4];
        float4 pvB = preB[c4];
        float4 w0 = smem_q[4*c4+0];
        float4 w1 = smem_q[4*c4+1];
        float4 w2 = smem_q[4*c4+2];
        float4 w3 = smem_q[4*c4+3];
        float h;
        h = fmaf(paX, w0.x, fmaf(paY, w0.y, fmaf(paZ, w0.z, pvA.x)));
        accA = fmaf(fmaxf(h, 0.f), w0.w, accA);
        h = fmaf(pbX, w0.x, fmaf(pbY, w0.y, fmaf(pbZ, w0.z, pvB.x)));
        accB = fmaf(fmaxf(h, 0.f), w0.w, accB);
        h = fmaf(paX, w1.x, fmaf(paY, w1.y, fmaf(paZ, w1.z, pvA.y)));
        accA = fmaf(fmaxf(h, 0.f), w1.w, accA);
        h = fmaf(pbX, w1.x, fmaf(pbY, w1.y, fmaf(pbZ, w1.z, pvB.y)));
        accB = fmaf(fmaxf(h, 0.f), w1.w, accB);
        h = fmaf(paX, w2.x, fmaf(paY, w2.y, fmaf(paZ, w2.z, pvA.z)));
        accA = fmaf(fmaxf(h, 0.f), w2.w, accA);
        h = fmaf(pbX, w2.x, fmaf(pbY, w2.y, fmaf(pbZ, w2.z, pvB.z)));
        accB = fmaf(fmaxf(h, 0.f), w2.w, accB);
        h = fmaf(paX, w3.x, fmaf(paY, w3.y, fmaf(paZ, w3.z, pvA.w)));
        accA = fmaf(fmaxf(h, 0.f), w3.w, accA);
        h = fmaf(pbX, w3.x, fmaf(pbY, w3.y, fmaf(pbZ, w3.z, pvB.w)));
        accB = fmaf(fmaxf(h, 0.f), w3.w, accB);
    }
    float evA = __expf(accA + bias2);
    float evB = __expf(accB + bias2);
    g_e[miA] = evA;
    g_e[miB] = evB;
    atomicAdd(&g_denom[iA], evA);
    atomicAdd(&g_denom[iB], evB);
}

// ========= prob-weighted scatter: 16-lane group owns one coarse point j =========
__global__ void __launch_bounds__(256)
scatter_kernel(const int* __restrict__ knn, float* __restrict__ out)
{
    const int tid  = threadIdx.x;
    const int lane = tid & 31, w = tid >> 5;
    const int half = lane >> 4;
    const int c4   = lane & 15;

    const int j  = blockIdx.x * 16 + w * 2 + half;
    const int mi = j * 16 + c4;

    const int   i_l = knn[mi];
    const float ev  = g_e[mi];
    const float dn  = g_denom[i_l];
    const float prob_l = ev * (dn > 0.f ? 1.0f / dn : 0.0f);

    const float4 u = *((const float4*)(g_upfeat + (size_t)j * 64) + c4);

    const int base = half << 4;
    #pragma unroll
    for (int k = 0; k < 16; k++) {
        float prob_b = __shfl_sync(0xffffffffu, prob_l, base + k);
        int   i_b    = __shfl_sync(0xffffffffu, i_l,    base + k);
        float4 val = make_float4(u.x * prob_b, u.y * prob_b, u.z * prob_b, u.w * prob_b);
        atomicAdd((float4*)(out + (size_t)i_b * 64) + c4, val);
    }
}

extern "C" void kernel_launch(void* const* d_in, const int* in_sizes, int n_in,
                              void* d_out, int out_size)
{
    const float* p1  = (const float*)d_in[0];
    const float* p2  = (const float*)d_in[1];
    const float* x1  = (const float*)d_in[2];
    const float* x2  = (const float*)d_in[3];
    const int*   knn = (const int*)  d_in[4];
    const float* w1  = (const float*)d_in[5];
    const float* b1  = (const float*)d_in[6];
    const float* g1  = (const float*)d_in[7];
    const float* be1 = (const float*)d_in[8];
    const float* m1  = (const float*)d_in[9];
    const float* v1  = (const float*)d_in[10];
    const float* w2  = (const float*)d_in[11];
    const float* b2  = (const float*)d_in[12];
    const float* g2  = (const float*)d_in[13];
    const float* be2 = (const float*)d_in[14];
    const float* m2  = (const float*)d_in[15];
    const float* v2  = (const float*)d_in[16];
    const float* ws1 = (const float*)d_in[17];
    const float* bs1 = (const float*)d_in[18];
    const float* gs  = (const float*)d_in[19];
    const float* bes = (const float*)d_in[20];
    const float* ms  = (const float*)d_in[21];
    const float* vs  = (const float*)d_in[22];
    const float* ws2 = (const float*)d_in[23];
    const float* bs2 = (const float*)d_in[24];
    float* out = (float*)d_out;

    // pack all weights/biases once + init denom + pack p1/p2
    prep_kernel<<<444, 256>>>(w1, b1, g1, be1, m1, v1,
                              w2, b2, g2, be2, m2, v2,
                              ws1, bs1, gs, bes, ms, vs, ws2, p1, p2);
    // ALL GEMM tiles (n2 first for balance; dual-A jobs share B loads)
    gemm_all_kernel<<<296, 256>>>(x1, x2, out);
    // logit + exp + denom (ILP-2)
    logit_kernel<<<MPAIR/512, 256>>>(knn, bs2);
    // prob-weighted scatter on top of y1
    scatter_kernel<<<N2/16, 256>>>(knn, out);
}

// round 16
// speedup vs baseline: 1.4184x; 1.4184x over previous
#include <cuda_runtime.h>
#include <cuda_bf16.h>
#include <cstdint>

#define N1 262144
#define N2 65536
#define KNN 16
#define MPAIR (N2*KNN)
#define EPSV 1e-5f

#define N2_JOBS2 (N2/256)          // 256  (each: upfeat+pre, 256 rows)
#define N1_JOBS2 (N1/256)          // 1024 (each: 256 rows)
#define ALL_JOBS (N1_JOBS2 + N2_JOBS2)

// ---- static scratch (no runtime allocation allowed) ----
__device__ float    g_upfeat[N2*64];   // relu(bn(x2@w2^T))
__device__ float    g_pre[N2*64];      // x2-part of shrinker linear
__device__ float    g_e[MPAIR];        // exp(logit)
__device__ float    g_denom[N1];       // softmax denominator
__device__ float4   g_p1q[N1];         // packed p1 (xyz_)
__device__ float4   g_p2q[N2];         // packed p2 (xyz_)
__device__ uint32_t g_packW[3*4096];   // prepacked+swizzled bf16 hi/lo weights (w1,w2,ws1)
__device__ float    g_fbW[3*64];       // folded biases
__device__ float4   g_sw34[64];        // shrinker (w3x,w3y,w3z,w2) per channel

// bf16 mma (baseline ISA, sm_80+; lowers to HMMA on sm_103 tensor pipe)
__device__ __forceinline__ void mma16816(float* d, const uint32_t* a, uint32_t b0, uint32_t b1) {
    asm volatile(
        "mma.sync.aligned.m16n8k16.row.col.f32.bf16.bf16.f32 "
        "{%0,%1,%2,%3}, {%4,%5,%6,%7}, {%8,%9}, {%0,%1,%2,%3};"
        : "+f"(d[0]), "+f"(d[1]), "+f"(d[2]), "+f"(d[3])
        : "r"(a[0]), "r"(a[1]), "r"(a[2]), "r"(a[3]), "r"(b0), "r"(b1));
}

// split (f0,f1) -> packed bf16 hi-pair + lo-pair (residual). Bit-trick version.
__device__ __forceinline__ void split2(float f0, float f1, uint32_t& hi, uint32_t& lo) {
    uint32_t hp;
    asm("cvt.rn.bf16x2.f32 %0, %1, %2;" : "=r"(hp) : "f"(f1), "f"(f0));
    float h0 = __uint_as_float(hp << 16);
    float h1 = __uint_as_float(hp & 0xFFFF0000u);
    float l0 = f0 - h0, l1 = f1 - h1;
    uint32_t lp;
    asm("cvt.rn.bf16x2.f32 %0, %1, %2;" : "=r"(lp) : "f"(l1), "f"(l0));
    hi = hp; lo = lp;
}

// ============ prep: pack all weights once + folded biases + sw34 + init ============
__global__ void __launch_bounds__(256)
prep_kernel(const float* __restrict__ w1, const float* __restrict__ b1,
            const float* __restrict__ g1, const float* __restrict__ be1,
            const float* __restrict__ m1, const float* __restrict__ v1,
            const float* __restrict__ w2, const float* __restrict__ b2,
            const float* __restrict__ g2, const float* __restrict__ be2,
            const float* __restrict__ m2, const float* __restrict__ v2,
            const float* __restrict__ ws1, const float* __restrict__ bs1,
            const float* __restrict__ gs, const float* __restrict__ bes,
            const float* __restrict__ ms, const float* __restrict__ vs,
            const float* __restrict__ ws2,
            const float* __restrict__ p1, const float* __restrict__ p2)
{
    const int gid = blockIdx.x * 256 + threadIdx.x;

    if (gid < 3 * 4096) {
        int mat = gid >> 12, idx = gid & 4095;
        const float *w, *gg, *vv; int wstride, wcol0;
        if (mat == 0)      { w = w1;  gg = g1; vv = v1; wstride = 64; wcol0 = 0; }
        else if (mat == 1) { w = w2;  gg = g2; vv = v2; wstride = 64; wcol0 = 0; }
        else               { w = ws1; gg = gs; vv = vs; wstride = 67; wcol0 = 3; }
        int row = idx >> 6, col = idx & 63;
        int r31 = row & 31;
        int ks = r31 >> 3, q = r31 & 7;
        int kk = 16 * ks + ((q < 4) ? 4 * q : 4 * (q - 4) + 2);
        float s  = gg[col] * rsqrtf(vv[col] + EPSV);
        float w0 = w[col * wstride + wcol0 + kk]     * s;
        float wv = w[col * wstride + wcol0 + kk + 1] * s;
        uint32_t hiw, low;
        split2(w0, wv, hiw, low);
        g_packW[mat * 4096 + row * 64 + (col ^ ((row & 3) << 3))] = (row < 32) ? hiw : low;
    } else if (gid < 3 * 4096 + 192) {
        int t = gid - 3 * 4096; int mat = t >> 6, c = t & 63;
        const float *bb, *gg, *be, *mm, *vv;
        if (mat == 0)      { bb = b1;  gg = g1; be = be1; mm = m1; vv = v1; }
        else if (mat == 1) { bb = b2;  gg = g2; be = be2; mm = m2; vv = v2; }
        else               { bb = bs1; gg = gs; be = bes; mm = ms; vv = vs; }
        float s = gg[c] * rsqrtf(vv[c] + EPSV);
        g_fbW[mat * 64 + c] = (bb[c] - mm[c]) * s + be[c];
    } else if (gid < 3 * 4096 + 192 + 64) {
        int c = gid - (3 * 4096 + 192);
        float s = gs[c] * rsqrtf(vs[c] + EPSV);
        g_sw34[c] = make_float4(ws1[c * 67] * s, ws1[c * 67 + 1] * s,
                                ws1[c * 67 + 2] * s, ws2[c]);
    }

    const int tot = gridDim.x * 256;
    for (int i = gid; i < N1; i += tot) {
        g_denom[i] = 0.0f;
        g_p1q[i] = make_float4(p1[3*i], p1[3*i+1], p1[3*i+2], 0.f);
    }
    for (int i = gid; i < N2; i += tot)
        g_p2q[i] = make_float4(p2[3*i], p2[3*i+1], p2[3*i+2], 0.f);
}

__device__ __forceinline__ void load_A(const float* __restrict__ x, int m0, int gq, int tq,
                                       uint32_t Ah[4][4], uint32_t Al[4][4])
{
    const float4* r0 = (const float4*)(x + (size_t)(m0 + gq) * 64);
    const float4* r1 = (const float4*)(x + (size_t)(m0 + gq + 8) * 64);
    #pragma unroll
    for (int ks = 0; ks < 4; ks++) {
        float4 v0 = r0[4 * ks + tq];
        float4 v1 = r1[4 * ks + tq];
        split2(v0.x, v0.y, Ah[ks][0], Al[ks][0]);
        split2(v1.x, v1.y, Ah[ks][1], Al[ks][1]);
        split2(v0.z, v0.w, Ah[ks][2], Al[ks][2]);
        split2(v1.z, v1.w, Ah[ks][3], Al[ks][3]);
    }
}

// DUAL-A 3-chain MMA over half the n-tiles. Per (ks,nt): 4 LDS serve 6 MMAs.
__device__ __forceinline__ void run_chains_dual(float acc0[4][4], float acc1[4][4],
                                                const uint32_t* packB,
                                                const uint32_t Ah0[4][4], const uint32_t Al0[4][4],
                                                const uint32_t Ah1[4][4], const uint32_t Al1[4][4],
                                                int gq, int tq, int nt0)
{
    const int csw = tq << 3;
    #pragma unroll
    for (int ks = 0; ks < 4; ks++) {
        const int rh0 = (8 * ks + tq) * 64;
        const int rh1 = (8 * ks + tq + 4) * 64;
        const int rl0 = (32 + 8 * ks + tq) * 64;
        const int rl1 = (32 + 8 * ks + tq + 4) * 64;
        #pragma unroll
        for (int nt = 0; nt < 4; nt++) {
            const int coff = (8 * (nt0 + nt) + gq) ^ csw;
            uint32_t bh0 = packB[rh0 + coff], bh1 = packB[rh1 + coff];
            uint32_t bl0 = packB[rl0 + coff], bl1 = packB[rl1 + coff];
            mma16816(acc0[nt], Ah0[ks], bh0, bh1);
            mma16816(acc1[nt], Ah1[ks], bh0, bh1);
            mma16816(acc0[nt], Ah0[ks], bl0, bl1);
            mma16816(acc1[nt], Ah1[ks], bl0, bl1);
            mma16816(acc0[nt], Al0[ks], bh0, bh1);
            mma16816(acc1[nt], Al1[ks], bh0, bh1);
        }
    }
}

// epilogue: folded bias read from GLOBAL (L1-cached, tiny)
__device__ __forceinline__ void epilogue_half(float acc[4][4], const float* __restrict__ fb,
                                              float* __restrict__ o, int m0, int gq, int tq,
                                              int nt0, bool relu)
{
    float* o0 = o + (size_t)(m0 + gq) * 64;
    float* o1 = o + (size_t)(m0 + gq + 8) * 64;
    #pragma unroll
    for (int nt = 0; nt < 4; nt++) {
        int col = 8 * (nt0 + nt) + 2 * tq;
        float2 fbp = *(const float2*)(fb + col);
        float2 u, v;
        u.x = acc[nt][0] + fbp.x; u.y = acc[nt][1] + fbp.y;
        v.x = acc[nt][2] + fbp.x; v.y = acc[nt][3] + fbp.y;
        if (relu) {
            u.x = fmaxf(u.x, 0.f); u.y = fmaxf(u.y, 0.f);
            v.x = fmaxf(v.x, 0.f); v.y = fmaxf(v.y, 0.f);
        }
        *(float2*)(o0 + col) = u;
        *(float2*)(o1 + col) = v;
    }
}

// ====== ALL GEMM tiles, 256-row dual-A jobs: 256 n2 jobs (first) + 1024 n1 jobs ======
__global__ void __launch_bounds__(256, 2)
gemm_all_kernel(const float* __restrict__ x1, const float* __restrict__ x2,
                float* __restrict__ outp)
{
    __shared__ uint32_t packW[3 * 4096];   // 48 KB
    const int tid = threadIdx.x, wid = tid >> 5, lane = tid & 31;
    const int gq = lane >> 2, tq = lane & 3;

    {
        const float4* src = (const float4*)g_packW;
        #pragma unroll
        for (int it = 0; it < 12; it++)
            ((float4*)packW)[it * 256 + tid] = src[it * 256 + tid];
    }
    __syncthreads();

    for (int job = blockIdx.x; job < ALL_JOBS; job += gridDim.x) {
        if (job < N2_JOBS2) {
            const int m0 = job * 256 + wid * 16;
            const int m1 = m0 + 128;
            uint32_t Ah0[4][4], Al0[4][4], Ah1[4][4], Al1[4][4];
            load_A(x2, m0, gq, tq, Ah0, Al0);
            load_A(x2, m1, gq, tq, Ah1, Al1);
            #pragma unroll
            for (int half = 0; half < 2; half++) {
                float acc0[4][4], acc1[4][4];
                #pragma unroll
                for (int nt = 0; nt < 4; nt++)
                    #pragma unroll
                    for (int r = 0; r < 4; r++) { acc0[nt][r] = 0.f; acc1[nt][r] = 0.f; }
                run_chains_dual(acc0, acc1, packW + 4096, Ah0, Al0, Ah1, Al1, gq, tq, half * 4);
                epilogue_half(acc0, g_fbW + 64, g_upfeat, m0, gq, tq, half * 4, true);
                epilogue_half(acc1, g_fbW + 64, g_upfeat, m1, gq, tq, half * 4, true);

                #pragma unroll
                for (int nt = 0; nt < 4; nt++)
                    #pragma unroll
                    for (int r = 0; r < 4; r++) { acc0[nt][r] = 0.f; acc1[nt][r] = 0.f; }
                run_chains_dual(acc0, acc1, packW + 8192, Ah0, Al0, Ah1, Al1, gq, tq, half * 4);
                epilogue_half(acc0, g_fbW + 128, g_pre, m0, gq, tq, half * 4, false);
                epilogue_half(acc1, g_fbW + 128, g_pre, m1, gq, tq, half * 4, false);
            }
        } else {
            const int m0 = (job - N2_JOBS2) * 256 + wid * 16;
            const int m1 = m0 + 128;
            uint32_t Ah0[4][4], Al0[4][4], Ah1[4][4], Al1[4][4];
            load_A(x1, m0, gq, tq, Ah0, Al0);
            load_A(x1, m1, gq, tq, Ah1, Al1);
            #pragma unroll
            for (int half = 0; half < 2; half++) {
                float acc0[4][4], acc1[4][4];
                #pragma unroll
                for (int nt = 0; nt < 4; nt++)
                    #pragma unroll
                    for (int r = 0; r < 4; r++) { acc0[nt][r] = 0.f; acc1[nt][r] = 0.f; }
                run_chains_dual(acc0, acc1, packW, Ah0, Al0, Ah1, Al1, gq, tq, half * 4);
                epilogue_half(acc0, g_fbW, outp, m0, gq, tq, half * 4, true);
                epilogue_half(acc1, g_fbW, outp, m1, gq, tq, half * 4, true);
            }
        }
    }
}

// ===================== logit + exp + denom (thread per pair, float4 weights) =====================
__global__ void __launch_bounds__(256)
logit_kernel(const int* __restrict__ knn, const float* __restrict__ bs2)
{
    __shared__ float4 smem_q[64];
    const int tid = threadIdx.x;
    if (tid < 64) smem_q[tid] = g_sw34[tid];
    __syncthreads();
    const float bias2 = bs2[0];

    const int mi = blockIdx.x * 256 + tid;
    const int j  = mi >> 4;
    const int i  = knn[mi];
    float4 pq = g_p1q[i];
    float4 qq = g_p2q[j];
    float prx = pq.x - qq.x, pry = pq.y - qq.y, prz = pq.z - qq.z;

    float acc = 0.0f;
    const float4* pre4 = (const float4*)(g_pre + (size_t)j * 64);
    #pragma unroll
    for (int c4 = 0; c4 < 16; c4++) {
        float4 pv = pre4[c4];
        float4 w0 = smem_q[4*c4+0];
        float4 w1 = smem_q[4*c4+1];
        float4 w2 = smem_q[4*c4+2];
        float4 w3 = smem_q[4*c4+3];
        float h;
        h = fmaf(prx, w0.x, fmaf(pry, w0.y, fmaf(prz, w0.z, pv.x)));
        acc = fmaf(fmaxf(h, 0.f), w0.w, acc);
        h = fmaf(prx, w1.x, fmaf(pry, w1.y, fmaf(prz, w1.z, pv.y)));
        acc = fmaf(fmaxf(h, 0.f), w1.w, acc);
        h = fmaf(prx, w2.x, fmaf(pry, w2.y, fmaf(prz, w2.z, pv.z)));
        acc = fmaf(fmaxf(h, 0.f), w2.w, acc);
        h = fmaf(prx, w3.x, fmaf(pry, w3.y, fmaf(prz, w3.z, pv.w)));
        acc = fmaf(fmaxf(h, 0.f), w3.w, acc);
    }
    float ev = __expf(acc + bias2);
    g_e[mi] = ev;
    atomicAdd(&g_denom[i], ev);
}

// ========= prob-weighted scatter: 16-lane group owns one coarse point j =========
__global__ void __launch_bounds__(256)
scatter_kernel(const int* __restrict__ knn, float* __restrict__ out)
{
    const int tid  = threadIdx.x;
    const int lane = tid & 31, w = tid >> 5;
    const int half = lane >> 4;
    const int c4   = lane & 15;

    const int j  = blockIdx.x * 16 + w * 2 + half;
    const int mi = j * 16 + c4;

    const int   i_l = knn[mi];
    const float ev  = g_e[mi];
    const float dn  = g_denom[i_l];
    const float prob_l = ev * (dn > 0.f ? 1.0f / dn : 0.0f);

    const float4 u = *((const float4*)(g_upfeat + (size_t)j * 64) + c4);

    const int base = half << 4;
    #pragma unroll
    for (int k = 0; k < 16; k++) {
        float prob_b = __shfl_sync(0xffffffffu, prob_l, base + k);
        int   i_b    = __shfl_sync(0xffffffffu, i_l,    base + k);
        float4 val = make_float4(u.x * prob_b, u.y * prob_b, u.z * prob_b, u.w * prob_b);
        atomicAdd((float4*)(out + (size_t)i_b * 64) + c4, val);
    }
}

extern "C" void kernel_launch(void* const* d_in, const int* in_sizes, int n_in,
                              void* d_out, int out_size)
{
    const float* p1  = (const float*)d_in[0];
    const float* p2  = (const float*)d_in[1];
    const float* x1  = (const float*)d_in[2];
    const float* x2  = (const float*)d_in[3];
    const int*   knn = (const int*)  d_in[4];
    const float* w1  = (const float*)d_in[5];
    const float* b1  = (const float*)d_in[6];
    const float* g1  = (const float*)d_in[7];
    const float* be1 = (const float*)d_in[8];
    const float* m1  = (const float*)d_in[9];
    const float* v1  = (const float*)d_in[10];
    const float* w2  = (const float*)d_in[11];
    const float* b2  = (const float*)d_in[12];
    const float* g2  = (const float*)d_in[13];
    const float* be2 = (const float*)d_in[14];
    const float* m2  = (const float*)d_in[15];
    const float* v2  = (const float*)d_in[16];
    const float* ws1 = (const float*)d_in[17];
    const float* bs1 = (const float*)d_in[18];
    const float* gs  = (const float*)d_in[19];
    const float* bes = (const float*)d_in[20];
    const float* ms  = (const float*)d_in[21];
    const float* vs  = (const float*)d_in[22];
    const float* ws2 = (const float*)d_in[23];
    const float* bs2 = (const float*)d_in[24];
    float* out = (float*)d_out;

    // pack all weights/biases once + init denom + pack p1/p2
    prep_kernel<<<444, 256>>>(w1, b1, g1, be1, m1, v1,
                              w2, b2, g2, be2, m2, v2,
                              ws1, bs1, gs, bes, ms, vs, ws2, p1, p2);
    // ALL GEMM tiles (n2 first for balance; dual-A jobs share B loads)
    gemm_all_kernel<<<296, 256>>>(x1, x2, out);
    // logit + exp + denom (ILP-1, proven)
    logit_kernel<<<MPAIR/256, 256>>>(knn, bs2);
    // prob-weighted scatter on top of y1
    scatter_kernel<<<N2/16, 256>>>(knn, out);
}